// round 15
// baseline (speedup 1.0000x reference)
#include <cuda_runtime.h>
#include <cuda_fp16.h>
#include <cstdint>

// ====================== helpers ======================
__device__ __forceinline__ uint32_t smem_u32(const void* p) {
    uint32_t a;
    asm("{ .reg .u64 t; cvta.to.shared.u64 t, %1; cvt.u32.u64 %0, t; }" : "=r"(a) : "l"(p));
    return a;
}
__device__ __forceinline__ void ldsm_x4t(uint32_t* d, uint32_t addr) {
    asm volatile("ldmatrix.sync.aligned.m8n8.x4.trans.shared.b16 {%0,%1,%2,%3}, [%4];"
        : "=r"(d[0]), "=r"(d[1]), "=r"(d[2]), "=r"(d[3]) : "r"(addr));
}
__device__ __forceinline__ void mma_f16(float* c, const uint32_t* a, uint32_t b0, uint32_t b1) {
    asm volatile(
        "mma.sync.aligned.m16n8k16.row.col.f32.f16.f16.f32 "
        "{%0,%1,%2,%3}, {%4,%5,%6,%7}, {%8,%9}, {%0,%1,%2,%3};"
        : "+f"(c[0]), "+f"(c[1]), "+f"(c[2]), "+f"(c[3])
        : "r"(a[0]), "r"(a[1]), "r"(a[2]), "r"(a[3]), "r"(b0), "r"(b1));
}
__device__ __forceinline__ uint32_t h2u(__half2 h) { return *reinterpret_cast<uint32_t*>(&h); }

// ====================== weight prep (once) ======================
// g_Bh: 128 rows (logical mma-k) x 64 fp16, 16B chunks XOR-swizzled by (k&7).
// Row k holds W[perm(k)][*]:  q=k&15, c=(q>>1)&3, e=q&1, hi8=q>>3 -> p = 16*(k>>4)+4c+2*hi8+e
__device__ unsigned char g_Bh[128 * 128];

__global__ void prep_weight_kernel(const float* __restrict__ weight) {
    int i = blockIdx.x * 256 + threadIdx.x;
    if (i < 8192) {
        int k = i >> 6, n = i & 63;
        int ks = k >> 4, q = k & 15;
        int c = (q >> 1) & 3, e = q & 1, hi8 = q >> 3;
        int p = 16 * ks + 4 * c + 2 * hi8 + e;
        __half h = __float2half_rn(weight[p * 64 + n]);
        int chunk = (n >> 3) ^ (k & 7);
        int off = k * 128 + chunk * 16 + (n & 7) * 2;
        *reinterpret_cast<__half*>(g_Bh + off) = h;
    }
}

// ====================== smem layout (persistent CTA, double-buffered H/W) ======================
// B    : 16384 B @ 0               (staged ONCE per CTA)
// H0/H1: 128 x 72 fp16 = 18432 B @ 16384 / 34816
// W0/W1: 32 blocks x 12 fp32 = 1536 B @ 53248 / 54784  (only s=1..3 columns used)
// bias : 256 B @ 56320  (staged once)
#define SM_B    0u
#define SM_H0   16384u
#define SM_H1   34816u
#define SM_W0   53248u
#define SM_W1   54784u
#define SM_BIAS 56320u
#define SMEM_TOTAL 56576
#define H_STRIDE 72   // halves; conflict-free STS.32 and LDS.128

__global__ void __launch_bounds__(256, 4) gcn_f16_kernel(
    const float* __restrict__ feat,
    const float* __restrict__ w,
    const float* __restrict__ bias,
    const float* __restrict__ alpha_p,
    float* __restrict__ out,
    int n_pool_blocks,
    int n_tiles)
{
    extern __shared__ unsigned char s_raw[];
    const uint32_t sb = smem_u32(s_raw);
    const int tid = threadIdx.x;
    const int wid = tid >> 5;
    const int lid = tid & 31;

    const float alpha = __ldg(alpha_p);

    // ---------- stage B tile (16KB) + bias ONCE ----------
    {
        const uint4* gbp = (const uint4*)&g_Bh[0];
        uint4* sp = (uint4*)(s_raw + SM_B);
        #pragma unroll
        for (int i = 0; i < 4; ++i) sp[tid + i * 256] = gbp[tid + i * 256];
        if (tid < 16) ((uint4*)(s_raw + SM_BIAS))[tid] = ((const uint4*)bias)[tid];
    }
    __syncthreads();

    // ---------- per-lane invariants ----------
    const int c  = lid & 3;
    const int rq = lid >> 2;
    const int bKrel = (lid & 7) + ((lid >> 3) & 1) * 8;
    const uint32_t bRow = (uint32_t)bKrel * 128u;
    const int bS  = bKrel & 7;
    const int bC0 = lid >> 4;
    // w staging invariants (96 threads; 3 uint4 per node-block covering floats 4..15)
    const int wBlk  = tid / 3;
    const int wPart = tid - wBlk * 3;

    int it = 0;
    for (int tile = blockIdx.x; tile < n_tiles; tile += gridDim.x, ++it) {
        const int buf = it & 1;
        unsigned char* Hraw = s_raw + (buf ? SM_H1 : SM_H0);
        unsigned char* Wraw = s_raw + (buf ? SM_W1 : SM_W0);

        // ---------- per-tile edge weights (12 floats/block) ----------
        if (tid < 96) {
            *(uint4*)(Wraw + (size_t)wBlk * 48 + wPart * 16) =
                *(const uint4*)(w + (size_t)tile * 512 + wBlk * 16 + 4 + wPart * 4);
        }

        // ---------- MMA: warp = 16 rows x 64 cols; hi-only (K=128) ----------
        float acc[8][4];
        #pragma unroll
        for (int t = 0; t < 8; ++t)
            #pragma unroll
            for (int i = 0; i < 4; ++i) acc[t][i] = 0.f;

        {
            const float* f0 = feat + (size_t)tile * (128 * 128)
                            + (size_t)(wid * 16 + rq) * 128 + 4 * c;
            const float* f1 = f0 + 8 * 128;

            #pragma unroll
            for (int ks = 0; ks < 8; ++ks) {
                float4 F0 = *(const float4*)(f0 + 16 * ks);
                float4 F1 = *(const float4*)(f1 + 16 * ks);
                uint32_t aH[4] = {
                    h2u(__floats2half2_rn(F0.x, F0.y)),
                    h2u(__floats2half2_rn(F1.x, F1.y)),
                    h2u(__floats2half2_rn(F0.z, F0.w)),
                    h2u(__floats2half2_rn(F1.z, F1.w)) };

                const uint32_t bkb = sb + SM_B + (uint32_t)(ks * 2048) + bRow;
                {
                    uint32_t b[8];
                    ldsm_x4t(b,     bkb + (uint32_t)(((0 + bC0) ^ bS) << 4));
                    ldsm_x4t(b + 4, bkb + (uint32_t)(((2 + bC0) ^ bS) << 4));
                    mma_f16(acc[0], aH, b[0], b[1]);
                    mma_f16(acc[1], aH, b[2], b[3]);
                    mma_f16(acc[2], aH, b[4], b[5]);
                    mma_f16(acc[3], aH, b[6], b[7]);
                }
                {
                    uint32_t b[8];
                    ldsm_x4t(b,     bkb + (uint32_t)(((4 + bC0) ^ bS) << 4));
                    ldsm_x4t(b + 4, bkb + (uint32_t)(((6 + bC0) ^ bS) << 4));
                    mma_f16(acc[4], aH, b[0], b[1]);
                    mma_f16(acc[5], aH, b[2], b[3]);
                    mma_f16(acc[6], aH, b[4], b[5]);
                    mma_f16(acc[7], aH, b[6], b[7]);
                }
            }
        }

        // ---------- accumulators -> smem H[buf] fp16 (stride 72 halves) ----------
        {
            __half* Hp = (__half*)Hraw;
            const int row = wid * 16 + (lid >> 2);
            const int cc  = (lid & 3) << 1;
            #pragma unroll
            for (int ns = 0; ns < 8; ++ns) {
                int col = ns * 8 + cc;
                *(__half2*)(Hp + (size_t)row * H_STRIDE + col)
                    = __floats2half2_rn(acc[ns][0], acc[ns][1]);
                *(__half2*)(Hp + (size_t)(row + 8) * H_STRIDE + col)
                    = __floats2half2_rn(acc[ns][2], acc[ns][3]);
            }
        }
        __syncthreads();   // single barrier per tile: H[buf] + W[buf] visible

        // ---------- epilogue: 32 node-blocks x 8 threads (8 cols/thread) ----------
        {
            const int tb = tid >> 3;
            const int q  = tid & 7;
            const int c0 = q << 3;
            const __half* Hb = (const __half*)Hraw + c0;
            const float* ws = (const float*)Wraw + tb * 12;
            const float* bs = (const float*)(s_raw + SM_BIAS);

            float a0[8], h1[8], h2[8], h3[8], bb[8];
            #define LOADH(dst, rowidx) do {                                          \
                uint4 _u = *(const uint4*)(Hb + (size_t)(rowidx) * H_STRIDE);        \
                const __half2* _hh = (const __half2*)&_u;                            \
                _Pragma("unroll")                                                    \
                for (int _j = 0; _j < 4; ++_j) {                                     \
                    float2 _f = __half22float2(_hh[_j]);                             \
                    (dst)[2 * _j] = _f.x; (dst)[2 * _j + 1] = _f.y;                  \
                } } while (0)
            LOADH(a0, 4 * tb);
            LOADH(h1, 4 * tb + 1);
            LOADH(h2, 4 * tb + 2);
            LOADH(h3, 4 * tb + 3);
            #undef LOADH
            *(float4*)(bb) = *(const float4*)(bs + c0);
            *(float4*)(bb + 4) = *(const float4*)(bs + c0 + 4);

            float pool[8];
            #pragma unroll
            for (int cc = 0; cc < 8; ++cc) pool[cc] = 0.f;
            #pragma unroll
            for (int j = 0; j < 4; ++j) {
                float w1 = ws[j], w2 = ws[4 + j], w3 = ws[8 + j];
                #pragma unroll
                for (int cc = 0; cc < 8; ++cc) {
                    float hv = fmaf(w1, h1[cc], fmaf(w2, h2[cc], w3 * h3[cc])) + bb[cc];
                    hv = (hv >= 0.f) ? hv : alpha * hv;
                    pool[cc] += hv;
                }
            }
            float pn = 0.f, an = 0.f;
            float aa[8];
            #pragma unroll
            for (int cc = 0; cc < 8; ++cc) {
                pool[cc] *= 0.25f;
                pn = fmaf(pool[cc], pool[cc], pn);
                float x = a0[cc] + bb[cc];
                x = (x >= 0.f) ? x : alpha * x;
                aa[cc] = x;
                an = fmaf(x, x, an);
            }
            #pragma unroll
            for (int o = 1; o < 8; o <<= 1) {
                pn += __shfl_xor_sync(0xFFFFFFFFu, pn, o);
                an += __shfl_xor_sync(0xFFFFFFFFu, an, o);
            }
            float pinv = 1.f / fmaxf(sqrtf(pn), 1e-12f);
            float ainv = 1.f / fmaxf(sqrtf(an), 1e-12f);

            size_t gb = (size_t)tile * 32 + tb;
            float* po = out + gb * 64 + c0;
            float* ao = out + (size_t)n_pool_blocks * 64 + gb * 64 + c0;
            *(float4*)(po)     = make_float4(pool[0]*pinv, pool[1]*pinv, pool[2]*pinv, pool[3]*pinv);
            *(float4*)(po + 4) = make_float4(pool[4]*pinv, pool[5]*pinv, pool[6]*pinv, pool[7]*pinv);
            *(float4*)(ao)     = make_float4(aa[0]*ainv, aa[1]*ainv, aa[2]*ainv, aa[3]*ainv);
            *(float4*)(ao + 4) = make_float4(aa[4]*ainv, aa[5]*ainv, aa[6]*ainv, aa[7]*ainv);
        }
    }
}

extern "C" void kernel_launch(void* const* d_in, const int* in_sizes, int n_in,
                              void* d_out, int out_size) {
    const float* feat   = (const float*)d_in[0];
    const float* w      = (const float*)d_in[1];
    const float* weight = (const float*)d_in[2];
    const float* bias   = (const float*)d_in[3];
    const float* alpha  = (const float*)d_in[4];
    float* out = (float*)d_out;

    int n_nodes = in_sizes[0] / 128;       // N = 524288
    int n_blk   = n_nodes / 4;             // B = 131072
    int n_tiles = n_nodes / 128;           // 4096 tiles

    int sms = 148;
    cudaDeviceGetAttribute(&sms, cudaDevAttrMultiProcessorCount, 0);
    int grid = sms * 4;                    // persistent: 4 CTAs/SM
    if (grid > n_tiles) grid = n_tiles;

    prep_weight_kernel<<<32, 256>>>(weight);

    cudaFuncSetAttribute(gcn_f16_kernel,
                         cudaFuncAttributeMaxDynamicSharedMemorySize, SMEM_TOTAL);
    gcn_f16_kernel<<<grid, 256, SMEM_TOTAL>>>(feat, w, bias, alpha, out, n_blk, n_tiles);
}

// round 16
// speedup vs baseline: 1.3030x; 1.3030x over previous
#include <cuda_runtime.h>
#include <cuda_fp16.h>
#include <cstdint>

// ====================== helpers ======================
__device__ __forceinline__ uint32_t smem_u32(const void* p) {
    uint32_t a;
    asm("{ .reg .u64 t; cvta.to.shared.u64 t, %1; cvt.u32.u64 %0, t; }" : "=r"(a) : "l"(p));
    return a;
}
__device__ __forceinline__ void ldsm_x4t(uint32_t* d, uint32_t addr) {
    asm volatile("ldmatrix.sync.aligned.m8n8.x4.trans.shared.b16 {%0,%1,%2,%3}, [%4];"
        : "=r"(d[0]), "=r"(d[1]), "=r"(d[2]), "=r"(d[3]) : "r"(addr));
}
__device__ __forceinline__ void mma_f16(float* c, const uint32_t* a, uint32_t b0, uint32_t b1) {
    asm volatile(
        "mma.sync.aligned.m16n8k16.row.col.f32.f16.f16.f32 "
        "{%0,%1,%2,%3}, {%4,%5,%6,%7}, {%8,%9}, {%0,%1,%2,%3};"
        : "+f"(c[0]), "+f"(c[1]), "+f"(c[2]), "+f"(c[3])
        : "r"(a[0]), "r"(a[1]), "r"(a[2]), "r"(a[3]), "r"(b0), "r"(b1));
}
__device__ __forceinline__ uint32_t h2u(__half2 h) { return *reinterpret_cast<uint32_t*>(&h); }

// ====================== smem layout (persistent CTA) ======================
// B   : 16384 B @ 0          (converted from weight ONCE per CTA)
// H   : 128 x 72 fp16 = 18432 B @ 16384
// w   : 2048 B @ 34816 (per tile)
// bias: 256 B @ 36864  (staged once)
#define SM_B    0u
#define SM_H    16384u
#define SM_W    34816u
#define SM_BIAS 36864u
#define SMEM_TOTAL 37120
#define H_STRIDE 72   // halves; conflict-free STS.32 and LDS.128

__global__ void __launch_bounds__(256, 4) gcn_f16_kernel(
    const float* __restrict__ feat,
    const float* __restrict__ w,
    const float* __restrict__ weight,
    const float* __restrict__ bias,
    const float* __restrict__ alpha_p,
    float* __restrict__ out,
    int n_pool_blocks,
    int n_tiles)
{
    extern __shared__ unsigned char s_raw[];
    const uint32_t sb = smem_u32(s_raw);
    const int tid = threadIdx.x;
    const int wid = tid >> 5;
    const int lid = tid & 31;

    const float alpha = __ldg(alpha_p);

    // ---------- convert weight -> swizzled fp16 B tile in smem, ONCE per CTA ----------
    // B row k (logical mma-k) holds W[perm(k)][*]:
    //   q=k&15, c=(q>>1)&3, e=q&1, hi8=q>>3 -> p = 16*(k>>4)+4c+2*hi8+e
    {
        #pragma unroll
        for (int it = 0; it < 32; ++it) {
            int i = tid + it * 256;               // 0..8191
            int k = i >> 6, n = i & 63;
            int ks = k >> 4, q = k & 15;
            int c4 = (q >> 1) & 3, e = q & 1, hi8 = q >> 3;
            int p = 16 * ks + 4 * c4 + 2 * hi8 + e;
            __half h = __float2half_rn(weight[p * 64 + n]);
            int chunk = (n >> 3) ^ (k & 7);
            *reinterpret_cast<__half*>(s_raw + SM_B + k * 128 + chunk * 16 + (n & 7) * 2) = h;
        }
        if (tid < 16) ((uint4*)(s_raw + SM_BIAS))[tid] = ((const uint4*)bias)[tid];
    }

    // ---------- per-lane invariants ----------
    const int c  = lid & 3;
    const int rq = lid >> 2;
    const int bKrel = (lid & 7) + ((lid >> 3) & 1) * 8;
    const uint32_t bRow = (uint32_t)bKrel * 128u;
    const int bS  = bKrel & 7;
    const int bC0 = lid >> 4;

    for (int tile = blockIdx.x; tile < n_tiles; tile += gridDim.x) {
        __syncthreads();   // staging visible (iter 0) / prev epilogue done (iter >0)

        // ---------- per-tile edge weights (2KB) ----------
        if (tid < 128) ((uint4*)(s_raw + SM_W))[tid] =
            ((const uint4*)(w + (size_t)tile * 512))[tid];

        // ---------- MMA: warp = 16 rows x 64 cols; hi-only (K=128) ----------
        float acc[8][4];
        #pragma unroll
        for (int t = 0; t < 8; ++t)
            #pragma unroll
            for (int i = 0; i < 4; ++i) acc[t][i] = 0.f;

        {
            const float* f0 = feat + (size_t)tile * (128 * 128)
                            + (size_t)(wid * 16 + rq) * 128 + 4 * c;
            const float* f1 = f0 + 8 * 128;

            #pragma unroll
            for (int ks = 0; ks < 8; ++ks) {
                float4 F0 = *(const float4*)(f0 + 16 * ks);
                float4 F1 = *(const float4*)(f1 + 16 * ks);
                uint32_t aH[4] = {
                    h2u(__floats2half2_rn(F0.x, F0.y)),
                    h2u(__floats2half2_rn(F1.x, F1.y)),
                    h2u(__floats2half2_rn(F0.z, F0.w)),
                    h2u(__floats2half2_rn(F1.z, F1.w)) };

                const uint32_t bkb = sb + SM_B + (uint32_t)(ks * 2048) + bRow;
                {
                    uint32_t b[8];
                    ldsm_x4t(b,     bkb + (uint32_t)(((0 + bC0) ^ bS) << 4));
                    ldsm_x4t(b + 4, bkb + (uint32_t)(((2 + bC0) ^ bS) << 4));
                    mma_f16(acc[0], aH, b[0], b[1]);
                    mma_f16(acc[1], aH, b[2], b[3]);
                    mma_f16(acc[2], aH, b[4], b[5]);
                    mma_f16(acc[3], aH, b[6], b[7]);
                }
                {
                    uint32_t b[8];
                    ldsm_x4t(b,     bkb + (uint32_t)(((4 + bC0) ^ bS) << 4));
                    ldsm_x4t(b + 4, bkb + (uint32_t)(((6 + bC0) ^ bS) << 4));
                    mma_f16(acc[4], aH, b[0], b[1]);
                    mma_f16(acc[5], aH, b[2], b[3]);
                    mma_f16(acc[6], aH, b[4], b[5]);
                    mma_f16(acc[7], aH, b[6], b[7]);
                }
            }
        }

        // ---------- accumulators -> smem H[128][64] fp16 (stride 72 halves) ----------
        {
            __half* Hp = (__half*)(s_raw + SM_H);
            const int row = wid * 16 + (lid >> 2);
            const int cc  = (lid & 3) << 1;
            #pragma unroll
            for (int ns = 0; ns < 8; ++ns) {
                int col = ns * 8 + cc;
                *(__half2*)(Hp + (size_t)row * H_STRIDE + col)
                    = __floats2half2_rn(acc[ns][0], acc[ns][1]);
                *(__half2*)(Hp + (size_t)(row + 8) * H_STRIDE + col)
                    = __floats2half2_rn(acc[ns][2], acc[ns][3]);
            }
        }
        __syncthreads();   // H + w visible to epilogue

        // ---------- epilogue: 32 node-blocks x 8 threads (8 cols/thread) ----------
        {
            const int tb = tid >> 3;
            const int q  = tid & 7;
            const int c0 = q << 3;
            const __half* Hb = (const __half*)(s_raw + SM_H) + c0;
            const float* ws = (const float*)(s_raw + SM_W) + tb * 16;
            const float* bs = (const float*)(s_raw + SM_BIAS);

            float a0[8], h1[8], h2[8], h3[8], bb[8];
            #define LOADH(dst, rowidx) do {                                          \
                uint4 _u = *(const uint4*)(Hb + (size_t)(rowidx) * H_STRIDE);        \
                const __half2* _hh = (const __half2*)&_u;                            \
                _Pragma("unroll")                                                    \
                for (int _j = 0; _j < 4; ++_j) {                                     \
                    float2 _f = __half22float2(_hh[_j]);                             \
                    (dst)[2 * _j] = _f.x; (dst)[2 * _j + 1] = _f.y;                  \
                } } while (0)
            LOADH(a0, 4 * tb);
            LOADH(h1, 4 * tb + 1);
            LOADH(h2, 4 * tb + 2);
            LOADH(h3, 4 * tb + 3);
            #undef LOADH
            *(float4*)(bb) = *(const float4*)(bs + c0);
            *(float4*)(bb + 4) = *(const float4*)(bs + c0 + 4);

            float pool[8];
            #pragma unroll
            for (int cc = 0; cc < 8; ++cc) pool[cc] = 0.f;
            #pragma unroll
            for (int j = 0; j < 4; ++j) {
                float w1 = ws[4 + j], w2 = ws[8 + j], w3 = ws[12 + j];
                #pragma unroll
                for (int cc = 0; cc < 8; ++cc) {
                    float hv = fmaf(w1, h1[cc], fmaf(w2, h2[cc], w3 * h3[cc])) + bb[cc];
                    hv = (hv >= 0.f) ? hv : alpha * hv;
                    pool[cc] += hv;
                }
            }
            float pn = 0.f, an = 0.f;
            float aa[8];
            #pragma unroll
            for (int cc = 0; cc < 8; ++cc) {
                pool[cc] *= 0.25f;
                pn = fmaf(pool[cc], pool[cc], pn);
                float x = a0[cc] + bb[cc];
                x = (x >= 0.f) ? x : alpha * x;
                aa[cc] = x;
                an = fmaf(x, x, an);
            }
            #pragma unroll
            for (int o = 1; o < 8; o <<= 1) {
                pn += __shfl_xor_sync(0xFFFFFFFFu, pn, o);
                an += __shfl_xor_sync(0xFFFFFFFFu, an, o);
            }
            float pinv = 1.f / fmaxf(sqrtf(pn), 1e-12f);
            float ainv = 1.f / fmaxf(sqrtf(an), 1e-12f);

            size_t gb = (size_t)tile * 32 + tb;
            float* po = out + gb * 64 + c0;
            float* ao = out + (size_t)n_pool_blocks * 64 + gb * 64 + c0;
            *(float4*)(po)     = make_float4(pool[0]*pinv, pool[1]*pinv, pool[2]*pinv, pool[3]*pinv);
            *(float4*)(po + 4) = make_float4(pool[4]*pinv, pool[5]*pinv, pool[6]*pinv, pool[7]*pinv);
            *(float4*)(ao)     = make_float4(aa[0]*ainv, aa[1]*ainv, aa[2]*ainv, aa[3]*ainv);
            *(float4*)(ao + 4) = make_float4(aa[4]*ainv, aa[5]*ainv, aa[6]*ainv, aa[7]*ainv);
        }
    }
}

extern "C" void kernel_launch(void* const* d_in, const int* in_sizes, int n_in,
                              void* d_out, int out_size) {
    const float* feat   = (const float*)d_in[0];
    const float* w      = (const float*)d_in[1];
    const float* weight = (const float*)d_in[2];
    const float* bias   = (const float*)d_in[3];
    const float* alpha  = (const float*)d_in[4];
    float* out = (float*)d_out;

    int n_nodes = in_sizes[0] / 128;       // N = 524288
    int n_blk   = n_nodes / 4;             // B = 131072
    int n_tiles = n_nodes / 128;           // 4096 tiles

    int sms = 148;
    cudaDeviceGetAttribute(&sms, cudaDevAttrMultiProcessorCount, 0);
    int grid = sms * 4;                    // persistent: 4 CTAs/SM
    if (grid > n_tiles) grid = n_tiles;

    cudaFuncSetAttribute(gcn_f16_kernel,
                         cudaFuncAttributeMaxDynamicSharedMemorySize, SMEM_TOTAL);
    gcn_f16_kernel<<<grid, 256, SMEM_TOTAL>>>(feat, w, weight, bias, alpha, out, n_blk, n_tiles);
}